// round 10
// baseline (speedup 1.0000x reference)
#include <cuda_runtime.h>
#include <cuda_bf16.h>
#include <cstdint>

// ---------------------------------------------------------------------------
// Problem constants
// ---------------------------------------------------------------------------
#define DD    101                 // inner dim
#define KO    101                 // output cols
#define KPAD  104                 // 13 * 8
#define BM    64                  // batch rows per tile
#define NTHR  128                 // 4 warps, each M=64 x ~26 cols

// B image: [kt][n][tg] float2 pairs = (A[k0+tg][n], A[k0+tg+4][n])
#define A_IMG_BYTES (13 * KPAD * 4 * 8)   // 43264

#define TILE_BYTES (BM * DD * 4)          // 25856
#define RAW_SLOT   26112                  // tile + 256 zeroed pad

// smem layout (bytes)
#define RAW0_OFF 0
#define RAW1_OFF RAW_SLOT                 // 26112
#define MBAR_OFF (2 * RAW_SLOT)           // 52224
#define SMEM_BYTES 52288

#define GRID 296                          // 2 CTAs/SM

__device__ __align__(16) unsigned char g_Apair[A_IMG_BYTES];

// ---------------------------------------------------------------------------
// Helpers
// ---------------------------------------------------------------------------
__device__ __forceinline__ uint32_t smem_u32(const void* p) {
    uint32_t a;
    asm("{ .reg .u64 t; cvta.to.shared.u64 t, %1; cvt.u32.u64 %0, t; }"
        : "=r"(a) : "l"(p));
    return a;
}
__device__ __forceinline__ void mbar_init(uint32_t m, uint32_t cnt) {
    asm volatile("mbarrier.init.shared.b64 [%0], %1;" :: "r"(m), "r"(cnt) : "memory");
}
__device__ __forceinline__ void mbar_expect_tx(uint32_t m, uint32_t bytes) {
    asm volatile("mbarrier.arrive.expect_tx.shared.b64 _, [%0], %1;"
                 :: "r"(m), "r"(bytes) : "memory");
}
__device__ __forceinline__ void mbar_wait(uint32_t m, uint32_t parity) {
    asm volatile(
        "{\n\t.reg .pred P;\n"
        "W_%=:\n\t"
        "mbarrier.try_wait.parity.acquire.cta.shared::cta.b64 P, [%0], %1;\n\t"
        "@!P bra W_%=;\n\t}"
        :: "r"(m), "r"(parity) : "memory");
}
__device__ __forceinline__ void bulk_g2s(uint32_t dst, const void* src,
                                         uint32_t bytes, uint32_t m) {
    asm volatile(
        "cp.async.bulk.shared::cta.global.mbarrier::complete_tx::bytes "
        "[%0], [%1], %2, [%3];"
        :: "r"(dst), "l"(src), "r"(bytes), "r"(m) : "memory");
}
__device__ __forceinline__ void bulk_s2g(void* gdst, uint32_t ssrc, uint32_t bytes) {
    asm volatile("cp.async.bulk.global.shared::cta.bulk_group [%0], [%1], %2;"
                 :: "l"(gdst), "r"(ssrc), "r"(bytes) : "memory");
}
#define S2G_COMMIT() asm volatile("cp.async.bulk.commit_group;" ::: "memory")
#define S2G_WAIT0()  asm volatile("cp.async.bulk.wait_group 0;" ::: "memory")

__device__ __forceinline__ float ldsf(uint32_t a) {
    float v;
    asm volatile("ld.shared.f32 %0, [%1];" : "=f"(v) : "r"(a));
    return v;
}
__device__ __forceinline__ void stsf(uint32_t a, float v) {
    asm volatile("st.shared.f32 [%0], %1;" :: "r"(a), "f"(v) : "memory");
}
__device__ __forceinline__ uint32_t to_tf32(float f) {
    uint32_t r;
    asm("cvt.rna.tf32.f32 %0, %1;" : "=r"(r) : "f"(f));
    return r;
}
__device__ __forceinline__ void mma_tf32(float* c, const uint32_t* a,
                                         const uint32_t* b) {
    asm volatile(
        "mma.sync.aligned.m16n8k8.row.col.f32.tf32.tf32.f32 "
        "{%0,%1,%2,%3}, {%4,%5,%6,%7}, {%8,%9}, {%0,%1,%2,%3};"
        : "+f"(c[0]), "+f"(c[1]), "+f"(c[2]), "+f"(c[3])
        : "r"(a[0]), "r"(a[1]), "r"(a[2]), "r"(a[3]), "r"(b[0]), "r"(b[1]));
}

// ---------------------------------------------------------------------------
// Kernel 1: fold constants -> tf32 operator, stored as frag-pair image:
//   g_Apair[kt][n][tg] = ( A[kt*8+tg][n], A[kt*8+tg+4][n] )   (float2)
// A_op[n,d] = ( sum_m Wre[n,m]*ReJ[m,d] - Wim[n,m]*ImJ[m,d] ) / 101
// ---------------------------------------------------------------------------
extern __shared__ float bsm[];
__global__ void build_A_kernel(const float* __restrict__ Wre,
                               const float* __restrict__ Wim,
                               const float* __restrict__ ReJ,
                               const float* __restrict__ ImJ) {
    float* sRe = bsm;
    float* sIm = bsm + 10201;
    float* sW  = bsm + 20402;
    const int tid = threadIdx.x;       // 128
    const int n   = blockIdx.x;        // 0..103

    for (int i = tid; i < 10201; i += 128) { sRe[i] = ReJ[i]; sIm[i] = ImJ[i]; }
    for (int i = tid; i < DD; i += 128) {
        sW[i]      = (n < KO) ? Wre[n * DD + i] : 0.0f;
        sW[DD + i] = (n < KO) ? Wim[n * DD + i] : 0.0f;
    }
    __syncthreads();

    const int d = tid;                 // k index
    if (d >= KPAD) return;
    float a = 0.0f;
    if (n < KO && d < DD) {
        float a0 = 0.f, a1 = 0.f;
        #pragma unroll 1
        for (int m = 0; m + 2 <= DD; m += 2) {
            a0 = fmaf(sW[m],        sRe[m*DD+d],     a0);
            a0 = fmaf(-sW[DD+m],    sIm[m*DD+d],     a0);
            a1 = fmaf(sW[m+1],      sRe[(m+1)*DD+d], a1);
            a1 = fmaf(-sW[DD+m+1],  sIm[(m+1)*DD+d], a1);
        }
        a0 = fmaf(sW[DD-1],     sRe[(DD-1)*DD+d], a0);
        a0 = fmaf(-sW[2*DD-1],  sIm[(DD-1)*DD+d], a0);
        a = (a0 + a1) * (1.0f / 101.0f);
    }
    const int kt   = d >> 3;
    const int r    = d & 7;
    const int tg   = r & 3;
    const int slot = r >> 2;
    *(uint32_t*)(g_Apair + kt * 3328 + n * 32 + tg * 8 + slot * 4) = to_tf32(a);
}

// ---------------------------------------------------------------------------
// Kernel 2: persistent tf32 GEMM. Each warp covers all M=64 rows (4 m-frags,
// permuted rows for conflict-free scalar LDS) and a 4/3/3/3 n-tile slice whose
// B fragments are REGISTER-RESIDENT (loaded once from global). No B smem.
//   frag f, group g -> physical rows f+4g and f+4g+32.
// ---------------------------------------------------------------------------
extern __shared__ unsigned char smem[];

__global__ void __launch_bounds__(NTHR, 2)
fourier_mma_kernel(const float* __restrict__ x, float* __restrict__ out,
                   int ntiles) {
    const int tid   = threadIdx.x;
    const int wid   = tid >> 5;       // 0..3
    const int lane  = tid & 31;
    const int g     = lane >> 2;
    const int tg    = lane & 3;
    const int start = (wid == 0) ? 0 : (1 + 3 * wid);   // 0,4,7,10
    const int NT    = (wid == 0) ? 4 : 3;
    const uint32_t sbase = smem_u32(smem);
    const uint32_t mb0 = sbase + MBAR_OFF;
    const uint32_t mb1 = sbase + MBAR_OFF + 8;

    // ---- load register-resident B panel (once, from global/L2) ----
    uint32_t b[4][13][2];
    #pragma unroll
    for (int nt = 0; nt < 4; ++nt) {
        if (nt < NT) {
            const unsigned char* p = g_Apair
                + (size_t)(((start + nt) * 8 + g) * 32 + tg * 8);
            #pragma unroll
            for (int kt = 0; kt < 13; ++kt) {
                float2 v = __ldg((const float2*)(p + kt * 3328));
                b[nt][kt][0] = __float_as_uint(v.x);
                b[nt][kt][1] = __float_as_uint(v.y);
            }
        }
    }

    // zero raw pad tails (K-tail overreads must be finite)
    for (int i = tid; i < (RAW_SLOT - TILE_BYTES) / 4; i += NTHR) {
        *(uint32_t*)(smem + RAW0_OFF + TILE_BYTES + i * 4) = 0;
        *(uint32_t*)(smem + RAW1_OFF + TILE_BYTES + i * 4) = 0;
    }
    if (tid == 0) { mbar_init(mb0, 1); mbar_init(mb1, 1); }
    __syncthreads();

    int t = blockIdx.x;
    if (tid == 0) {
        mbar_expect_tx(mb0, TILE_BYTES);
        bulk_g2s(sbase + RAW0_OFF, (const char*)x + (size_t)t * TILE_BYTES,
                 TILE_BYTES, mb0);
    }

    // a-frag bases: frag f -> physical rows f+4g (+32), k word = tg
    uint32_t ra[4];
    #pragma unroll
    for (int f = 0; f < 4; ++f)
        ra[f] = (uint32_t)((f + 4 * g) * DD + tg) * 4u;

    int buf = 0;
    uint32_t par0 = 0, par1 = 0;
    #pragma unroll 1
    for (; t < ntiles; t += GRID) {
        const int tn = t + GRID;
        if (tn < ntiles && tid == 0) {
            S2G_WAIT0();      // target buffer was S2G source two phases ago
            const uint32_t mb_nxt = buf ? mb0 : mb1;
            mbar_expect_tx(mb_nxt, TILE_BYTES);
            bulk_g2s(sbase + (buf ? RAW0_OFF : RAW1_OFF),
                     (const char*)x + (size_t)tn * TILE_BYTES, TILE_BYTES, mb_nxt);
        }
        if (buf) { mbar_wait(mb1, par1); par1 ^= 1; }
        else     { mbar_wait(mb0, par0); par0 ^= 1; }

        float acc[4][4][4];   // [m-frag][n-tile][frag reg]
        #pragma unroll
        for (int f = 0; f < 4; ++f)
            #pragma unroll
            for (int nt = 0; nt < 4; ++nt)
                #pragma unroll
                for (int i = 0; i < 4; ++i) acc[f][nt][i] = 0.0f;

        const uint32_t rawb = sbase + (buf ? RAW1_OFF : RAW0_OFF);

        #pragma unroll
        for (int kt = 0; kt < 13; ++kt) {
            const uint32_t ko = (uint32_t)kt * 32u;
            uint32_t a[4][4];
            #pragma unroll
            for (int f = 0; f < 4; ++f) {
                const uint32_t rx = rawb + ra[f] + ko;
                a[f][0] = to_tf32(ldsf(rx));
                a[f][1] = to_tf32(ldsf(rx + 12928));      // +32 rows
                a[f][2] = to_tf32(ldsf(rx + 16));         // +4 k cols
                a[f][3] = to_tf32(ldsf(rx + 12928 + 16));
            }
            #pragma unroll
            for (int nt = 0; nt < 4; ++nt) {
                if (nt < NT) {
                    #pragma unroll
                    for (int f = 0; f < 4; ++f)
                        mma_tf32(acc[f][nt], a[f], b[nt][kt]);
                }
            }
        }

        // ---- epilogue: stage exact [64 x 101] fp32 image into raw[buf] ----
        __syncthreads();   // all warps done reading this buffer's x
        {
            #pragma unroll
            for (int f = 0; f < 4; ++f) {
                const uint32_t st0 = rawb + (uint32_t)((f + 4 * g) * KO) * 4u;
                #pragma unroll
                for (int nt = 0; nt < 4; ++nt) {
                    if (nt >= NT) break;
                    const int col = (start + nt) * 8 + tg * 2;
                    if (col < KO) {
                        stsf(st0 + (uint32_t)col * 4u, acc[f][nt][0]);
                        stsf(st0 + 12928u + (uint32_t)col * 4u, acc[f][nt][2]);
                        if (col + 1 < KO) {
                            stsf(st0 + (uint32_t)(col + 1) * 4u, acc[f][nt][1]);
                            stsf(st0 + 12928u + (uint32_t)(col + 1) * 4u,
                                 acc[f][nt][3]);
                        }
                    }
                }
            }
        }
        __syncthreads();   // full tile staged
        if (tid == 0) {
            asm volatile("fence.proxy.async.shared::cta;" ::: "memory");
            bulk_s2g(out + (size_t)t * (BM * KO), rawb, TILE_BYTES);
            S2G_COMMIT();
        }
        buf ^= 1;
    }
    if (tid == 0) S2G_WAIT0();
}

// ---------------------------------------------------------------------------
// Launch
// ---------------------------------------------------------------------------
extern "C" void kernel_launch(void* const* d_in, const int* in_sizes, int n_in,
                              void* d_out, int out_size) {
    const float* x   = (const float*)d_in[0];
    const float* Wre = (const float*)d_in[1];
    const float* Wim = (const float*)d_in[2];
    const float* ReJ = (const float*)d_in[3];
    const float* ImJ = (const float*)d_in[4];
    float* out = (float*)d_out;

    const int B = in_sizes[0] / DD;       // 262144
    const int ntiles = B / BM;            // 4096

    const int build_smem = (20402 + 2 * DD) * (int)sizeof(float);
    cudaFuncSetAttribute(build_A_kernel,
                         cudaFuncAttributeMaxDynamicSharedMemorySize, build_smem);
    build_A_kernel<<<KPAD, 128, build_smem>>>(Wre, Wim, ReJ, ImJ);

    cudaFuncSetAttribute(fourier_mma_kernel,
                         cudaFuncAttributeMaxDynamicSharedMemorySize, SMEM_BYTES);
    fourier_mma_kernel<<<GRID, NTHR, SMEM_BYTES>>>(x, out, ntiles);
    (void)n_in; (void)out_size;
}

// round 11
// speedup vs baseline: 1.1286x; 1.1286x over previous
#include <cuda_runtime.h>
#include <cuda_bf16.h>
#include <cstdint>

// ---------------------------------------------------------------------------
// Problem constants
// ---------------------------------------------------------------------------
#define DD    101                 // inner dim
#define KO    101                 // output cols
#define KPAD  104                 // 13 * 8
#define BM    64                  // batch rows per tile
#define NTHR  384                 // 3 groups x 4 warps
#define NGRP  3

// B image: [kt][n][tg] float2 pairs = (A[k0+tg][n], A[k0+tg+4][n])
#define A_IMG_BYTES (13 * KPAD * 4 * 8)   // 43264

#define TILE_BYTES (BM * DD * 4)          // 25856
#define RAW_SLOT   26112                  // tile + 256 zeroed pad

// smem layout (bytes): [A image][6 raw slots][mbars]
#define AIMG_OFF 0
#define RAWBASE  A_IMG_BYTES              // 43264
#define MBAR_OFF (RAWBASE + 6 * RAW_SLOT) // 199936  (6 tile mbars + A mbar)
#define SMEM_BYTES 200064

#define GRID 148                          // 1 CTA/SM
#define NSTREAM (GRID * NGRP)             // 444 tile streams

__device__ __align__(16) unsigned char g_Apair[A_IMG_BYTES];

// ---------------------------------------------------------------------------
// Helpers
// ---------------------------------------------------------------------------
__device__ __forceinline__ uint32_t smem_u32(const void* p) {
    uint32_t a;
    asm("{ .reg .u64 t; cvta.to.shared.u64 t, %1; cvt.u32.u64 %0, t; }"
        : "=r"(a) : "l"(p));
    return a;
}
__device__ __forceinline__ void mbar_init(uint32_t m, uint32_t cnt) {
    asm volatile("mbarrier.init.shared.b64 [%0], %1;" :: "r"(m), "r"(cnt) : "memory");
}
__device__ __forceinline__ void mbar_expect_tx(uint32_t m, uint32_t bytes) {
    asm volatile("mbarrier.arrive.expect_tx.shared.b64 _, [%0], %1;"
                 :: "r"(m), "r"(bytes) : "memory");
}
__device__ __forceinline__ void mbar_wait(uint32_t m, uint32_t parity) {
    asm volatile(
        "{\n\t.reg .pred P;\n"
        "W_%=:\n\t"
        "mbarrier.try_wait.parity.acquire.cta.shared::cta.b64 P, [%0], %1;\n\t"
        "@!P bra W_%=;\n\t}"
        :: "r"(m), "r"(parity) : "memory");
}
__device__ __forceinline__ void bulk_g2s(uint32_t dst, const void* src,
                                         uint32_t bytes, uint32_t m) {
    asm volatile(
        "cp.async.bulk.shared::cta.global.mbarrier::complete_tx::bytes "
        "[%0], [%1], %2, [%3];"
        :: "r"(dst), "l"(src), "r"(bytes), "r"(m) : "memory");
}
__device__ __forceinline__ void bulk_s2g(void* gdst, uint32_t ssrc, uint32_t bytes) {
    asm volatile("cp.async.bulk.global.shared::cta.bulk_group [%0], [%1], %2;"
                 :: "l"(gdst), "r"(ssrc), "r"(bytes) : "memory");
}
#define S2G_COMMIT() asm volatile("cp.async.bulk.commit_group;" ::: "memory")
#define S2G_WAIT0()  asm volatile("cp.async.bulk.wait_group 0;" ::: "memory")
#define GRP_BAR(id)  asm volatile("bar.sync %0, 128;" :: "r"(id) : "memory")

__device__ __forceinline__ float ldsf(uint32_t a) {
    float v;
    asm volatile("ld.shared.f32 %0, [%1];" : "=f"(v) : "r"(a));
    return v;
}
__device__ __forceinline__ void ldsv2(uint32_t* r, uint32_t a) {
    asm volatile("ld.shared.v2.b32 {%0,%1}, [%2];"
                 : "=r"(r[0]), "=r"(r[1]) : "r"(a));
}
__device__ __forceinline__ void stsf(uint32_t a, float v) {
    asm volatile("st.shared.f32 [%0], %1;" :: "r"(a), "f"(v) : "memory");
}
__device__ __forceinline__ uint32_t to_tf32(float f) {
    uint32_t r;
    asm("cvt.rna.tf32.f32 %0, %1;" : "=r"(r) : "f"(f));
    return r;
}
__device__ __forceinline__ void mma_tf32(float* c, const uint32_t* a,
                                         const uint32_t* b) {
    asm volatile(
        "mma.sync.aligned.m16n8k8.row.col.f32.tf32.tf32.f32 "
        "{%0,%1,%2,%3}, {%4,%5,%6,%7}, {%8,%9}, {%0,%1,%2,%3};"
        : "+f"(c[0]), "+f"(c[1]), "+f"(c[2]), "+f"(c[3])
        : "r"(a[0]), "r"(a[1]), "r"(a[2]), "r"(a[3]), "r"(b[0]), "r"(b[1]));
}

// ---------------------------------------------------------------------------
// Kernel 1: fold constants -> tf32 operator, stored as frag-pair image:
//   g_Apair[kt][n][tg] = ( A[kt*8+tg][n], A[kt*8+tg+4][n] )   (float2)
// A_op[n,d] = ( sum_m Wre[n,m]*ReJ[m,d] - Wim[n,m]*ImJ[m,d] ) / 101
// ---------------------------------------------------------------------------
extern __shared__ float bsm[];
__global__ void build_A_kernel(const float* __restrict__ Wre,
                               const float* __restrict__ Wim,
                               const float* __restrict__ ReJ,
                               const float* __restrict__ ImJ) {
    float* sRe = bsm;
    float* sIm = bsm + 10201;
    float* sW  = bsm + 20402;
    const int tid = threadIdx.x;       // 128
    const int n   = blockIdx.x;        // 0..103

    for (int i = tid; i < 10201; i += 128) { sRe[i] = ReJ[i]; sIm[i] = ImJ[i]; }
    for (int i = tid; i < DD; i += 128) {
        sW[i]      = (n < KO) ? Wre[n * DD + i] : 0.0f;
        sW[DD + i] = (n < KO) ? Wim[n * DD + i] : 0.0f;
    }
    __syncthreads();

    const int d = tid;                 // k index
    if (d >= KPAD) return;
    float a = 0.0f;
    if (n < KO && d < DD) {
        float a0 = 0.f, a1 = 0.f;
        #pragma unroll 1
        for (int m = 0; m + 2 <= DD; m += 2) {
            a0 = fmaf(sW[m],        sRe[m*DD+d],     a0);
            a0 = fmaf(-sW[DD+m],    sIm[m*DD+d],     a0);
            a1 = fmaf(sW[m+1],      sRe[(m+1)*DD+d], a1);
            a1 = fmaf(-sW[DD+m+1],  sIm[(m+1)*DD+d], a1);
        }
        a0 = fmaf(sW[DD-1],     sRe[(DD-1)*DD+d], a0);
        a0 = fmaf(-sW[2*DD-1],  sIm[(DD-1)*DD+d], a0);
        a = (a0 + a1) * (1.0f / 101.0f);
    }
    const int kt   = d >> 3;
    const int r    = d & 7;
    const int tg   = r & 3;
    const int slot = r >> 2;
    *(uint32_t*)(g_Apair + kt * 3328 + n * 32 + tg * 8 + slot * 4) = to_tf32(a);
}

// ---------------------------------------------------------------------------
// Kernel 2: one 384-thread CTA per SM = 3 independent 4-warp tile pipelines
// (each identical to the R9 winner: M=32 warp tiles, permuted conflict-free
// a-loads, paired-B LDS.64, TMA in/out) sharing ONE smem A panel.
// Groups synchronize only via named barriers (ids 1..3).
// ---------------------------------------------------------------------------
extern __shared__ unsigned char smem[];

__global__ void __launch_bounds__(NTHR, 1)
fourier_mma_kernel(const float* __restrict__ x, float* __restrict__ out,
                   int ntiles) {
    const int tid   = threadIdx.x;
    const int grp   = tid >> 7;       // 0..2
    const int gtid  = tid & 127;
    const int w4    = (tid >> 5) & 3; // warp within group
    const int lane  = tid & 31;
    const int g     = lane >> 2;
    const int tg    = lane & 3;
    const int mwarp = w4 >> 1;        // row classes {2m, 2m+1}
    const int nhalf = w4 & 1;
    const int NT    = nhalf ? 6 : 7;
    const int barid = grp + 1;
    const uint32_t sbase = smem_u32(smem);

    const uint32_t raw0 = sbase + RAWBASE + (uint32_t)(2 * grp) * RAW_SLOT;
    const uint32_t mb0  = sbase + MBAR_OFF + (uint32_t)(2 * grp) * 8;
    const uint32_t mb1  = mb0 + 8;
    const uint32_t mbA  = sbase + MBAR_OFF + 48;

    // zero all raw pad tails (K-tail overreads must be finite)
    for (int i = tid; i < 6 * (RAW_SLOT - TILE_BYTES) / 4; i += NTHR) {
        int slot = i / ((RAW_SLOT - TILE_BYTES) / 4);
        int off  = i - slot * ((RAW_SLOT - TILE_BYTES) / 4);
        *(uint32_t*)(smem + RAWBASE + slot * RAW_SLOT + TILE_BYTES + off * 4) = 0;
    }
    if (tid == 0) {
        #pragma unroll
        for (int i = 0; i < 6; ++i) mbar_init(sbase + MBAR_OFF + i * 8, 1);
        mbar_init(mbA, 1);
    }
    __syncthreads();

    const int s = blockIdx.x * NGRP + grp;   // tile stream id
    int t = s;
    if (tid == 0) {                          // A panel, own barrier
        mbar_expect_tx(mbA, A_IMG_BYTES);
        bulk_g2s(sbase + AIMG_OFF, g_Apair, A_IMG_BYTES, mbA);
    }
    if (gtid == 0 && t < ntiles) {           // each group's first tile
        mbar_expect_tx(mb0, TILE_BYTES);
        bulk_g2s(raw0, (const char*)x + (size_t)t * TILE_BYTES, TILE_BYTES, mb0);
    }
    mbar_wait(mbA, 0);
    __syncthreads();                         // A visible to all groups

    // a-frag bases: frag f, row = (2m+f) + 4g, k word = tg (conflict-free)
    const uint32_t ra0 = (uint32_t)(((2 * mwarp + 0) + 4 * g) * DD + tg) * 4u;
    const uint32_t ra1 = (uint32_t)(((2 * mwarp + 1) + 4 * g) * DD + tg) * 4u;
    // b pair base: [kt=0][n = nhalf*56 + g][tg]
    const uint32_t rbA = sbase + AIMG_OFF
        + (uint32_t)((nhalf * 56 + g) * 32 + tg * 8);

    int buf = 0;
    uint32_t par0 = 0, par1 = 0;
    #pragma unroll 1
    for (; t < ntiles; t += NSTREAM) {
        const int tn = t + NSTREAM;
        if (tn < ntiles && gtid == 0) {
            S2G_WAIT0();      // target buffer was this group's S2G source
            const uint32_t mb_nxt = buf ? mb0 : mb1;
            mbar_expect_tx(mb_nxt, TILE_BYTES);
            bulk_g2s(raw0 + (uint32_t)(buf ^ 1) * RAW_SLOT,
                     (const char*)x + (size_t)tn * TILE_BYTES, TILE_BYTES, mb_nxt);
        }
        if (buf) { mbar_wait(mb1, par1); par1 ^= 1; }
        else     { mbar_wait(mb0, par0); par0 ^= 1; }

        float acc[2][7][4];
        #pragma unroll
        for (int f = 0; f < 2; ++f)
            #pragma unroll
            for (int nt = 0; nt < 7; ++nt)
                #pragma unroll
                for (int i = 0; i < 4; ++i) acc[f][nt][i] = 0.0f;

        const uint32_t rawb = raw0 + (uint32_t)buf * RAW_SLOT;
        const uint32_t rx0 = rawb + ra0;
        const uint32_t rx1 = rawb + ra1;

        #pragma unroll
        for (int kt = 0; kt < 13; ++kt) {
            const uint32_t ko = (uint32_t)kt * 32u;
            uint32_t a0[4], a1[4];
            a0[0] = to_tf32(ldsf(rx0 + ko));
            a0[1] = to_tf32(ldsf(rx0 + ko + 12928));       // +32 rows
            a0[2] = to_tf32(ldsf(rx0 + ko + 16));          // +4 k cols
            a0[3] = to_tf32(ldsf(rx0 + ko + 12928 + 16));
            a1[0] = to_tf32(ldsf(rx1 + ko));
            a1[1] = to_tf32(ldsf(rx1 + ko + 12928));
            a1[2] = to_tf32(ldsf(rx1 + ko + 16));
            a1[3] = to_tf32(ldsf(rx1 + ko + 12928 + 16));

            const uint32_t kb = rbA + (uint32_t)kt * 3328u;
            uint32_t b[7][2];
            #pragma unroll
            for (int nt = 0; nt < 7; ++nt)
                if (nt < NT) ldsv2(b[nt], kb + (uint32_t)nt * 256u);

            #pragma unroll
            for (int nt = 0; nt < 7; ++nt)
                if (nt < NT) mma_tf32(acc[0][nt], a0, b[nt]);
            #pragma unroll
            for (int nt = 0; nt < 7; ++nt)
                if (nt < NT) mma_tf32(acc[1][nt], a1, b[nt]);
        }

        // ---- epilogue: stage exact [64 x 101] fp32 image into raw[buf] ----
        GRP_BAR(barid);    // group warps done reading this buffer's x
        {
            #pragma unroll
            for (int f = 0; f < 2; ++f) {
                const uint32_t st0 = rawb
                    + (uint32_t)(((2 * mwarp + f) + 4 * g) * KO) * 4u;
                #pragma unroll
                for (int nt = 0; nt < 7; ++nt) {
                    if (nt >= NT) break;
                    const int col = nhalf * 56 + nt * 8 + tg * 2;
                    if (col < KO) {
                        stsf(st0 + (uint32_t)col * 4u, acc[f][nt][0]);
                        stsf(st0 + 12928u + (uint32_t)col * 4u, acc[f][nt][2]);
                        if (col + 1 < KO) {
                            stsf(st0 + (uint32_t)(col + 1) * 4u, acc[f][nt][1]);
                            stsf(st0 + 12928u + (uint32_t)(col + 1) * 4u,
                                 acc[f][nt][3]);
                        }
                    }
                }
            }
        }
        GRP_BAR(barid);    // full tile staged (bar.sync drains STS)
        if (gtid == 0) {
            asm volatile("fence.proxy.async.shared::cta;" ::: "memory");
            bulk_s2g(out + (size_t)t * (BM * KO), rawb, TILE_BYTES);
            S2G_COMMIT();
        }
        buf ^= 1;
    }
    if (gtid == 0) S2G_WAIT0();
}

// ---------------------------------------------------------------------------
// Launch
// ---------------------------------------------------------------------------
extern "C" void kernel_launch(void* const* d_in, const int* in_sizes, int n_in,
                              void* d_out, int out_size) {
    const float* x   = (const float*)d_in[0];
    const float* Wre = (const float*)d_in[1];
    const float* Wim = (const float*)d_in[2];
    const float* ReJ = (const float*)d_in[3];
    const float* ImJ = (const float*)d_in[4];
    float* out = (float*)d_out;

    const int B = in_sizes[0] / DD;       // 262144
    const int ntiles = B / BM;            // 4096

    const int build_smem = (20402 + 2 * DD) * (int)sizeof(float);
    cudaFuncSetAttribute(build_A_kernel,
                         cudaFuncAttributeMaxDynamicSharedMemorySize, build_smem);
    build_A_kernel<<<KPAD, 128, build_smem>>>(Wre, Wim, ReJ, ImJ);

    cudaFuncSetAttribute(fourier_mma_kernel,
                         cudaFuncAttributeMaxDynamicSharedMemorySize, SMEM_BYTES);
    fourier_mma_kernel<<<GRID, NTHR, SMEM_BYTES>>>(x, out, ntiles);
    (void)n_in; (void)out_size;
}

// round 12
// speedup vs baseline: 1.3947x; 1.2357x over previous
#include <cuda_runtime.h>
#include <cuda_bf16.h>
#include <cstdint>

// ---------------------------------------------------------------------------
// Problem constants
// ---------------------------------------------------------------------------
#define DD    101                 // inner dim
#define KO    101                 // output cols
#define KPAD  104                 // 13 * 8
#define BM    64                  // batch rows per tile
#define NTHR  384                 // 3 groups x 4 warps
#define NGRP  3

// B image: [kt][n][tg] float2 pairs = (A[k0+tg][n], A[k0+tg+4][n])
#define A_IMG_BYTES (13 * KPAD * 4 * 8)   // 43264

#define TILE_BYTES (BM * DD * 4)          // 25856
#define RAW_SLOT   26112                  // tile + 256 zeroed pad

// smem layout (bytes): [A image][6 raw slots][mbars]
#define AIMG_OFF 0
#define RAWBASE  A_IMG_BYTES              // 43264
#define MBAR_OFF (RAWBASE + 6 * RAW_SLOT) // 199936  (6 tile mbars + A mbar)
#define SMEM_BYTES 200064

#define GRID 148                          // 1 CTA/SM
#define NSTREAM (GRID * NGRP)             // 444 tile streams

__device__ __align__(16) unsigned char g_Apair[A_IMG_BYTES];

// ---------------------------------------------------------------------------
// Helpers
// ---------------------------------------------------------------------------
__device__ __forceinline__ uint32_t smem_u32(const void* p) {
    uint32_t a;
    asm("{ .reg .u64 t; cvta.to.shared.u64 t, %1; cvt.u32.u64 %0, t; }"
        : "=r"(a) : "l"(p));
    return a;
}
__device__ __forceinline__ void mbar_init(uint32_t m, uint32_t cnt) {
    asm volatile("mbarrier.init.shared.b64 [%0], %1;" :: "r"(m), "r"(cnt) : "memory");
}
__device__ __forceinline__ void mbar_expect_tx(uint32_t m, uint32_t bytes) {
    asm volatile("mbarrier.arrive.expect_tx.shared.b64 _, [%0], %1;"
                 :: "r"(m), "r"(bytes) : "memory");
}
__device__ __forceinline__ void mbar_wait(uint32_t m, uint32_t parity) {
    asm volatile(
        "{\n\t.reg .pred P;\n"
        "W_%=:\n\t"
        "mbarrier.try_wait.parity.acquire.cta.shared::cta.b64 P, [%0], %1;\n\t"
        "@!P bra W_%=;\n\t}"
        :: "r"(m), "r"(parity) : "memory");
}
__device__ __forceinline__ void bulk_g2s(uint32_t dst, const void* src,
                                         uint32_t bytes, uint32_t m) {
    asm volatile(
        "cp.async.bulk.shared::cta.global.mbarrier::complete_tx::bytes "
        "[%0], [%1], %2, [%3];"
        :: "r"(dst), "l"(src), "r"(bytes), "r"(m) : "memory");
}
__device__ __forceinline__ void bulk_s2g(void* gdst, uint32_t ssrc, uint32_t bytes) {
    asm volatile("cp.async.bulk.global.shared::cta.bulk_group [%0], [%1], %2;"
                 :: "l"(gdst), "r"(ssrc), "r"(bytes) : "memory");
}
#define S2G_COMMIT() asm volatile("cp.async.bulk.commit_group;" ::: "memory")
#define S2G_WAIT0()  asm volatile("cp.async.bulk.wait_group 0;" ::: "memory")
#define GRP_BAR(id)  asm volatile("bar.sync %0, 128;" :: "r"(id) : "memory")

__device__ __forceinline__ float ldsf(uint32_t a) {
    float v;
    asm volatile("ld.shared.f32 %0, [%1];" : "=f"(v) : "r"(a));
    return v;
}
__device__ __forceinline__ void ldsv2(uint32_t* r, uint32_t a) {
    asm volatile("ld.shared.v2.b32 {%0,%1}, [%2];"
                 : "=r"(r[0]), "=r"(r[1]) : "r"(a));
}
__device__ __forceinline__ void stsf(uint32_t a, float v) {
    asm volatile("st.shared.f32 [%0], %1;" :: "r"(a), "f"(v) : "memory");
}
__device__ __forceinline__ uint32_t to_tf32(float f) {
    uint32_t r;
    asm("cvt.rna.tf32.f32 %0, %1;" : "=r"(r) : "f"(f));
    return r;
}
__device__ __forceinline__ void mma_tf32(float* c, const uint32_t* a,
                                         const uint32_t* b) {
    asm volatile(
        "mma.sync.aligned.m16n8k8.row.col.f32.tf32.tf32.f32 "
        "{%0,%1,%2,%3}, {%4,%5,%6,%7}, {%8,%9}, {%0,%1,%2,%3};"
        : "+f"(c[0]), "+f"(c[1]), "+f"(c[2]), "+f"(c[3])
        : "r"(a[0]), "r"(a[1]), "r"(a[2]), "r"(a[3]), "r"(b[0]), "r"(b[1]));
}

// ---------------------------------------------------------------------------
// Kernel 1 (closed form): the join matrices ReJ/ImJ are sparse selections:
//   ReJ[n,n]=1 (n<=50); ReJ[m,101-m]=1 (51<=m<=100)
//   ImJ[m,m+50]=1 (1<=m<=50); ImJ[m,151-m]=-1 (51<=m<=100)
// =>  A[n,d] = ( Wre[n,d] + [d>=1]*Wre[n,101-d] ) / 101          d <= 50
//     A[n,d] = ( Wim[n,151-d] - Wim[n,d-50] ) / 101              51 <= d <= 100
// Stored tf32-rounded into the frag-pair image:
//   g_Apair[kt][n][tg] = ( A[kt*8+tg][n], A[kt*8+tg+4][n] )   (float2 slots)
// (image index: row index of pair = d (k dim), col = n)
// ---------------------------------------------------------------------------
__global__ void build_A_kernel(const float* __restrict__ Wre,
                               const float* __restrict__ Wim) {
    const int n = blockIdx.x;       // 0..103  (output col of A image)
    const int d = threadIdx.x;      // 0..103  (k index)
    float a = 0.0f;
    if (n < KO && d < DD) {
        if (d <= 50) {
            a = Wre[n * DD + d];
            if (d >= 1) a += Wre[n * DD + (101 - d)];
        } else {
            a = Wim[n * DD + (151 - d)] - Wim[n * DD + (d - 50)];
        }
        a *= (1.0f / 101.0f);
    }
    const int kt   = d >> 3;
    const int r    = d & 7;
    const int tg   = r & 3;
    const int slot = r >> 2;        // 0: k0+tg, 1: k0+tg+4
    *(uint32_t*)(g_Apair + kt * 3328 + n * 32 + tg * 8 + slot * 4) = to_tf32(a);
}

// ---------------------------------------------------------------------------
// Kernel 2: one 384-thread CTA per SM = 3 independent 4-warp tile pipelines
// (M=32 warp tiles, permuted conflict-free a-loads, paired-B LDS.64, TMA
// in/out) sharing ONE smem A panel. Groups sync via named barriers.
// ---------------------------------------------------------------------------
extern __shared__ unsigned char smem[];

__global__ void __launch_bounds__(NTHR, 1)
fourier_mma_kernel(const float* __restrict__ x, float* __restrict__ out,
                   int ntiles) {
    const int tid   = threadIdx.x;
    const int grp   = tid >> 7;       // 0..2
    const int gtid  = tid & 127;
    const int w4    = (tid >> 5) & 3; // warp within group
    const int lane  = tid & 31;
    const int g     = lane >> 2;
    const int tg    = lane & 3;
    const int mwarp = w4 >> 1;        // row classes {2m, 2m+1}
    const int nhalf = w4 & 1;
    const int NT    = nhalf ? 6 : 7;
    const int barid = grp + 1;
    const uint32_t sbase = smem_u32(smem);

    const uint32_t raw0 = sbase + RAWBASE + (uint32_t)(2 * grp) * RAW_SLOT;
    const uint32_t mb0  = sbase + MBAR_OFF + (uint32_t)(2 * grp) * 8;
    const uint32_t mb1  = mb0 + 8;
    const uint32_t mbA  = sbase + MBAR_OFF + 48;

    // zero all raw pad tails (K-tail overreads must be finite)
    for (int i = tid; i < 6 * (RAW_SLOT - TILE_BYTES) / 4; i += NTHR) {
        int slot = i / ((RAW_SLOT - TILE_BYTES) / 4);
        int off  = i - slot * ((RAW_SLOT - TILE_BYTES) / 4);
        *(uint32_t*)(smem + RAWBASE + slot * RAW_SLOT + TILE_BYTES + off * 4) = 0;
    }
    if (tid == 0) {
        #pragma unroll
        for (int i = 0; i < 6; ++i) mbar_init(sbase + MBAR_OFF + i * 8, 1);
        mbar_init(mbA, 1);
    }
    __syncthreads();

    const int s = blockIdx.x * NGRP + grp;   // tile stream id
    int t = s;
    if (tid == 0) {                          // A panel, own barrier
        mbar_expect_tx(mbA, A_IMG_BYTES);
        bulk_g2s(sbase + AIMG_OFF, g_Apair, A_IMG_BYTES, mbA);
    }
    if (gtid == 0 && t < ntiles) {           // each group's first tile
        mbar_expect_tx(mb0, TILE_BYTES);
        bulk_g2s(raw0, (const char*)x + (size_t)t * TILE_BYTES, TILE_BYTES, mb0);
    }
    mbar_wait(mbA, 0);
    __syncthreads();                         // A visible to all groups

    // a-frag bases: frag f, row = (2m+f) + 4g, k word = tg (conflict-free)
    const uint32_t ra0 = (uint32_t)(((2 * mwarp + 0) + 4 * g) * DD + tg) * 4u;
    const uint32_t ra1 = (uint32_t)(((2 * mwarp + 1) + 4 * g) * DD + tg) * 4u;
    // b pair base: [kt=0][n = nhalf*56 + g][tg]
    const uint32_t rbA = sbase + AIMG_OFF
        + (uint32_t)((nhalf * 56 + g) * 32 + tg * 8);

    int buf = 0;
    uint32_t par0 = 0, par1 = 0;
    #pragma unroll 1
    for (; t < ntiles; t += NSTREAM) {
        const int tn = t + NSTREAM;
        if (tn < ntiles && gtid == 0) {
            S2G_WAIT0();      // target buffer was this group's S2G source
            const uint32_t mb_nxt = buf ? mb0 : mb1;
            mbar_expect_tx(mb_nxt, TILE_BYTES);
            bulk_g2s(raw0 + (uint32_t)(buf ^ 1) * RAW_SLOT,
                     (const char*)x + (size_t)tn * TILE_BYTES, TILE_BYTES, mb_nxt);
        }
        if (buf) { mbar_wait(mb1, par1); par1 ^= 1; }
        else     { mbar_wait(mb0, par0); par0 ^= 1; }

        float acc[2][7][4];
        #pragma unroll
        for (int f = 0; f < 2; ++f)
            #pragma unroll
            for (int nt = 0; nt < 7; ++nt)
                #pragma unroll
                for (int i = 0; i < 4; ++i) acc[f][nt][i] = 0.0f;

        const uint32_t rawb = raw0 + (uint32_t)buf * RAW_SLOT;
        const uint32_t rx0 = rawb + ra0;
        const uint32_t rx1 = rawb + ra1;

        #pragma unroll
        for (int kt = 0; kt < 13; ++kt) {
            const uint32_t ko = (uint32_t)kt * 32u;
            uint32_t a0[4], a1[4];
            a0[0] = to_tf32(ldsf(rx0 + ko));
            a0[1] = to_tf32(ldsf(rx0 + ko + 12928));       // +32 rows
            a0[2] = to_tf32(ldsf(rx0 + ko + 16));          // +4 k cols
            a0[3] = to_tf32(ldsf(rx0 + ko + 12928 + 16));
            a1[0] = to_tf32(ldsf(rx1 + ko));
            a1[1] = to_tf32(ldsf(rx1 + ko + 12928));
            a1[2] = to_tf32(ldsf(rx1 + ko + 16));
            a1[3] = to_tf32(ldsf(rx1 + ko + 12928 + 16));

            const uint32_t kb = rbA + (uint32_t)kt * 3328u;
            uint32_t b[7][2];
            #pragma unroll
            for (int nt = 0; nt < 7; ++nt)
                if (nt < NT) ldsv2(b[nt], kb + (uint32_t)nt * 256u);

            #pragma unroll
            for (int nt = 0; nt < 7; ++nt)
                if (nt < NT) mma_tf32(acc[0][nt], a0, b[nt]);
            #pragma unroll
            for (int nt = 0; nt < 7; ++nt)
                if (nt < NT) mma_tf32(acc[1][nt], a1, b[nt]);
        }

        // ---- epilogue: stage exact [64 x 101] fp32 image into raw[buf] ----
        GRP_BAR(barid);    // group warps done reading this buffer's x
        {
            #pragma unroll
            for (int f = 0; f < 2; ++f) {
                const uint32_t st0 = rawb
                    + (uint32_t)(((2 * mwarp + f) + 4 * g) * KO) * 4u;
                #pragma unroll
                for (int nt = 0; nt < 7; ++nt) {
                    if (nt >= NT) break;
                    const int col = nhalf * 56 + nt * 8 + tg * 2;
                    if (col < KO) {
                        stsf(st0 + (uint32_t)col * 4u, acc[f][nt][0]);
                        stsf(st0 + 12928u + (uint32_t)col * 4u, acc[f][nt][2]);
                        if (col + 1 < KO) {
                            stsf(st0 + (uint32_t)(col + 1) * 4u, acc[f][nt][1]);
                            stsf(st0 + 12928u + (uint32_t)(col + 1) * 4u,
                                 acc[f][nt][3]);
                        }
                    }
                }
            }
        }
        GRP_BAR(barid);    // full tile staged (bar.sync drains STS)
        if (gtid == 0) {
            asm volatile("fence.proxy.async.shared::cta;" ::: "memory");
            bulk_s2g(out + (size_t)t * (BM * KO), rawb, TILE_BYTES);
            S2G_COMMIT();
        }
        buf ^= 1;
    }
    if (gtid == 0) S2G_WAIT0();
}

// ---------------------------------------------------------------------------
// Launch
// ---------------------------------------------------------------------------
extern "C" void kernel_launch(void* const* d_in, const int* in_sizes, int n_in,
                              void* d_out, int out_size) {
    const float* x   = (const float*)d_in[0];
    const float* Wre = (const float*)d_in[1];
    const float* Wim = (const float*)d_in[2];
    float* out = (float*)d_out;

    const int B = in_sizes[0] / DD;       // 262144
    const int ntiles = B / BM;            // 4096

    build_A_kernel<<<KPAD, KPAD>>>(Wre, Wim);

    cudaFuncSetAttribute(fourier_mma_kernel,
                         cudaFuncAttributeMaxDynamicSharedMemorySize, SMEM_BYTES);
    fourier_mma_kernel<<<GRID, NTHR, SMEM_BYTES>>>(x, out, ntiles);
    (void)n_in; (void)out_size;
}